// round 2
// baseline (speedup 1.0000x reference)
#include <cuda_runtime.h>
#include <math.h>

#define NIMG 16
#define NPIX 65536
#define DH 64
#define PB 32            // pixels per batch-round
#define CH 37            // chunks per image -> 16*37 = 592 CTAs = 4*148
#define NBATCH (NPIX / PB)   // 2048

__device__ float g_hist[NIMG * 3 * DH * DH];   // [img][3][64][64]
__device__ float g_hn[8];

// ---------------------------------------------------------------------------
// Heavy kernel: accumulate the three shared-weight histograms per image.
//   U = w(ur), V = w(vr), W = w(vr-ur) = w(lg-lb)
//   H1 = sum iy*U(x)V  (ch r),  H2 = sum iy*U(x)W (ch g, row-reversed),
//   H3 = sum iy*V(x)W  (ch b, both-reversed).
// Reversals are index permutations identical for x and y -> loss-invariant,
// so they are never applied.
// ---------------------------------------------------------------------------
__global__ __launch_bounds__(256, 2)
void hist_kernel(const float* __restrict__ x, const float* __restrict__ y)
{
    __shared__ float sU [PB * DH];   // w(ur)
    __shared__ float sV [PB * DH];   // w(vr)           (row operand of H3)
    __shared__ float sVi[PB * DH];   // iy * w(vr)      (col operand of H1)
    __shared__ float sWi[PB * DH];   // iy * w(lg-lb)   (col operand of H2,H3)
    __shared__ float pU[PB], pV[PB], pW[PB], pIy[PB];

    const int img   = blockIdx.x / CH;
    const int chunk = blockIdx.x - img * CH;
    const float* base = (img < 8 ? x : y) + (size_t)(img & 7) * (3 * NPIX);

    const int tid = threadIdx.x;
    const int ty  = tid >> 4;      // 0..15 -> row tile (4 rows)
    const int tx  = tid & 15;      // 0..15 -> col tile (4 cols)

    float a1[4][4], a2[4][4], a3[4][4];
#pragma unroll
    for (int i = 0; i < 4; i++)
#pragma unroll
        for (int j = 0; j < 4; j++) { a1[i][j] = 0.f; a2[i][j] = 0.f; a3[i][j] = 0.f; }

    for (int t = chunk; t < NBATCH; t += CH) {
        const int n0 = t * PB;

        // ---- per-pixel preprocessing (32 threads) ----
        if (tid < PB) {
            int n = n0 + tid;
            float r = base[n]            + 1e-6f;
            float g = base[NPIX + n]     + 1e-6f;
            float b = base[2 * NPIX + n] + 1e-6f;
            float lr = __logf(r), lg = __logf(g), lb = __logf(b);
            pU [tid] = lr - lg;                       // ur
            pV [tid] = lr - lb;                       // vr
            pW [tid] = lg - lb;                       // vr - ur
            pIy[tid] = sqrtf(fmaf(r, r, fmaf(g, g, b * b)));
        }
        __syncthreads();

        // ---- weight phase: 32 pixels x 64 bins x 3 types ----
#pragma unroll
        for (int k = 0; k < 8; k++) {
            int task = tid + k * 256;          // 0..2047
            int p = task >> 6;
            int j = task & 63;
            float c  = fmaf((float)j, 6.0f / 63.0f, -3.0f);
            float iy = pIy[p];
            float du = (pU[p] - c) * 50.0f;    // 1/FALL_OFF = 50
            float dv = (pV[p] - c) * 50.0f;
            float dw = (pW[p] - c) * 50.0f;
            float wu = __fdividef(1.0f, fmaf(du, du, 1.0f));
            float wv = __fdividef(1.0f, fmaf(dv, dv, 1.0f));
            float ww = __fdividef(1.0f, fmaf(dw, dw, 1.0f));
            sU [task] = wu;
            sV [task] = wv;
            sVi[task] = wv * iy;
            sWi[task] = ww * iy;
        }
        __syncthreads();

        // ---- outer-product accumulate: 48 FFMA per pixel per thread ----
#pragma unroll 2
        for (int p = 0; p < PB; p++) {
            float4 u4  = *(const float4*)&sU [p * DH + 4 * ty];
            float4 v4  = *(const float4*)&sV [p * DH + 4 * ty];
            float4 vi4 = *(const float4*)&sVi[p * DH + 4 * tx];
            float4 wi4 = *(const float4*)&sWi[p * DH + 4 * tx];
            float u [4] = {u4.x,  u4.y,  u4.z,  u4.w};
            float v [4] = {v4.x,  v4.y,  v4.z,  v4.w};
            float vi[4] = {vi4.x, vi4.y, vi4.z, vi4.w};
            float wi[4] = {wi4.x, wi4.y, wi4.z, wi4.w};
#pragma unroll
            for (int i = 0; i < 4; i++)
#pragma unroll
                for (int j = 0; j < 4; j++) {
                    a1[i][j] = fmaf(u[i], vi[j], a1[i][j]);
                    a2[i][j] = fmaf(u[i], wi[j], a2[i][j]);
                    a3[i][j] = fmaf(v[i], wi[j], a3[i][j]);
                }
        }
        // no trailing sync needed: next round's first __syncthreads() orders
        // this round's sU/sV reads against next round's writes
    }

    // ---- epilogue: per-CTA partials -> global hist via atomics ----
    float* h = g_hist + img * 3 * (DH * DH);
#pragma unroll
    for (int i = 0; i < 4; i++)
#pragma unroll
        for (int j = 0; j < 4; j++) {
            int idx = (4 * ty + i) * DH + 4 * tx + j;
            atomicAdd(h +               idx, a1[i][j]);
            atomicAdd(h + 1 * DH * DH + idx, a2[i][j]);
            atomicAdd(h + 2 * DH * DH + idx, a3[i][j]);
        }
}

// ---------------------------------------------------------------------------
// Per-batch Hellinger reduction: one block per batch element.
// ---------------------------------------------------------------------------
__global__ void reduce_kernel()
{
    __shared__ float red[256];
    __shared__ float sSx, sSy;
    const int b   = blockIdx.x;
    const int tid = threadIdx.x;
    const float* hx = g_hist + (size_t)b       * (3 * DH * DH);
    const float* hy = g_hist + (size_t)(8 + b) * (3 * DH * DH);

    float sx = 0.f, sy = 0.f;
    for (int i = tid; i < 3 * DH * DH; i += 256) { sx += hx[i]; sy += hy[i]; }

    red[tid] = sx; __syncthreads();
    for (int s = 128; s > 0; s >>= 1) { if (tid < s) red[tid] += red[tid + s]; __syncthreads(); }
    if (tid == 0) sSx = red[0];
    __syncthreads();

    red[tid] = sy; __syncthreads();
    for (int s = 128; s > 0; s >>= 1) { if (tid < s) red[tid] += red[tid + s]; __syncthreads(); }
    if (tid == 0) sSy = red[0];
    __syncthreads();

    const float rx = 1.0f / sSx;
    const float ry = 1.0f / sSy;

    float ss = 0.f;
    for (int i = tid; i < 3 * DH * DH; i += 256) {
        float d = sqrtf(hy[i] * ry) - sqrtf(hx[i] * rx);
        ss = fmaf(d, d, ss);
    }
    red[tid] = ss; __syncthreads();
    for (int s = 128; s > 0; s >>= 1) { if (tid < s) red[tid] += red[tid + s]; __syncthreads(); }
    if (tid == 0) g_hn[b] = sqrtf(red[0]) * 0.70710678118654752f;  // sqrt(0.5)
}

__global__ void final_kernel(float* __restrict__ out)
{
    float s = 0.f;
#pragma unroll
    for (int b = 0; b < 8; b++) s += g_hn[b];
    out[0] = s * 0.125f;
}

// ---------------------------------------------------------------------------
extern "C" void kernel_launch(void* const* d_in, const int* in_sizes, int n_in,
                              void* d_out, int out_size)
{
    const float* x = (const float*)d_in[0];
    const float* y = (const float*)d_in[1];

    void* hptr = nullptr;
    cudaGetSymbolAddress(&hptr, g_hist);
    cudaMemsetAsync(hptr, 0, sizeof(float) * NIMG * 3 * DH * DH);

    hist_kernel<<<NIMG * CH, 256>>>(x, y);
    reduce_kernel<<<8, 256>>>();
    final_kernel<<<1, 1>>>((float*)d_out);
}

// round 4
// speedup vs baseline: 1.5651x; 1.5651x over previous
#include <cuda_runtime.h>
#include <math.h>

#define NIMG 16
#define NPIX 65536
#define DH 64
#define PB 32            // pixels per batch-round
#define CH 37            // chunks per image -> 16*37 = 592 CTAs = 4*148
#define NBATCH (NPIX / PB)   // 2048

__device__ float g_hist[NIMG * 3 * DH * DH];   // [img][3][64][64]
__device__ float g_hn[8];

// packed f32x2 helpers (sm_103a)
#define FMA_F32X2(d, a, b) \
    asm("fma.rn.f32x2 %0, %1, %2, %0;" : "+l"(d) : "l"(a), "l"(b))
#define PACK2(out, lo, hi) \
    asm("mov.b64 %0, {%1, %2};" : "=l"(out) : "f"(lo), "f"(hi))
#define UNPACK2(lo, hi, in) \
    asm("mov.b64 {%0, %1}, %2;" : "=f"(lo), "=f"(hi) : "l"(in))

// ---------------------------------------------------------------------------
// Heavy kernel: accumulate the three shared-weight histograms per image.
//   U = w(ur), V = w(vr), W = w(lg-lb)
//   H1 = sum iy*U(x)V, H2 = sum iy*U(x)W (row-rev), H3 = sum iy*V(x)W (rev both)
// Reversals are identical fixed permutations for x and y -> loss-invariant,
// so they are never applied.
// Inner loop uses packed fma.rn.f32x2: column operands are adjacent in smem
// (float4 = 2 packed f32x2), row operands broadcast-packed once per pixel.
// ---------------------------------------------------------------------------
__global__ __launch_bounds__(256, 2)
void hist_kernel(const float* __restrict__ x, const float* __restrict__ y)
{
    __shared__ float sU [PB * DH];   // w(ur)
    __shared__ float sV [PB * DH];   // w(vr)           (row operand of H3)
    __shared__ float sVi[PB * DH];   // iy * w(vr)      (col operand of H1)
    __shared__ float sWi[PB * DH];   // iy * w(lg-lb)   (col operand of H2,H3)
    __shared__ float pU[PB], pV[PB], pW[PB], pIy[PB];

    const int img   = blockIdx.x / CH;
    const int chunk = blockIdx.x - img * CH;
    const float* base = (img < 8 ? x : y) + (size_t)(img & 7) * (3 * NPIX);

    const int tid = threadIdx.x;
    const int ty  = tid >> 4;      // 0..15 -> row tile (4 rows)
    const int tx  = tid & 15;      // 0..15 -> col tile (4 cols = 2 f32x2 pairs)

    // packed accumulators: [row][col-pair], 3 hists x 4 x 2 = 24 x 64-bit
    unsigned long long a1[4][2], a2[4][2], a3[4][2];
#pragma unroll
    for (int i = 0; i < 4; i++)
#pragma unroll
        for (int j = 0; j < 2; j++) { a1[i][j] = 0ull; a2[i][j] = 0ull; a3[i][j] = 0ull; }

    for (int t = chunk; t < NBATCH; t += CH) {
        const int n0 = t * PB;

        // ---- per-pixel preprocessing (32 threads) ----
        if (tid < PB) {
            int n = n0 + tid;
            float r = base[n]            + 1e-6f;
            float g = base[NPIX + n]     + 1e-6f;
            float b = base[2 * NPIX + n] + 1e-6f;
            float lr = __logf(r), lg = __logf(g), lb = __logf(b);
            pU [tid] = lr - lg;                       // ur
            pV [tid] = lr - lb;                       // vr
            pW [tid] = lg - lb;                       // vr - ur
            pIy[tid] = sqrtf(fmaf(r, r, fmaf(g, g, b * b)));
        }
        __syncthreads();

        // ---- weight phase: 32 pixels x 64 bins x 3 types ----
#pragma unroll
        for (int k = 0; k < 8; k++) {
            int task = tid + k * 256;          // 0..2047
            int p = task >> 6;
            int j = task & 63;
            float c  = fmaf((float)j, 6.0f / 63.0f, -3.0f);
            float iy = pIy[p];
            float du = (pU[p] - c) * 50.0f;    // 1/FALL_OFF = 50
            float dv = (pV[p] - c) * 50.0f;
            float dw = (pW[p] - c) * 50.0f;
            float wu = __fdividef(1.0f, fmaf(du, du, 1.0f));
            float wv = __fdividef(1.0f, fmaf(dv, dv, 1.0f));
            float ww = __fdividef(1.0f, fmaf(dw, dw, 1.0f));
            sU [task] = wu;
            sV [task] = wv;
            sVi[task] = wv * iy;
            sWi[task] = ww * iy;
        }
        __syncthreads();

        // ---- outer-product accumulate: 24 FFMA2 per pixel per thread ----
#pragma unroll 2
        for (int p = 0; p < PB; p++) {
            float4 u4 = *(const float4*)&sU[p * DH + 4 * ty];
            float4 v4 = *(const float4*)&sV[p * DH + 4 * ty];
            // column operands: float4 = two packed f32x2, already adjacent
            ulonglong2 vi = *(const ulonglong2*)&sVi[p * DH + 4 * tx];
            ulonglong2 wi = *(const ulonglong2*)&sWi[p * DH + 4 * tx];

            unsigned long long uu[4], vv[4];
            float ua[4] = {u4.x, u4.y, u4.z, u4.w};
            float va[4] = {v4.x, v4.y, v4.z, v4.w};
#pragma unroll
            for (int i = 0; i < 4; i++) {
                PACK2(uu[i], ua[i], ua[i]);
                PACK2(vv[i], va[i], va[i]);
            }
#pragma unroll
            for (int i = 0; i < 4; i++) {
                FMA_F32X2(a1[i][0], uu[i], vi.x);
                FMA_F32X2(a1[i][1], uu[i], vi.y);
                FMA_F32X2(a2[i][0], uu[i], wi.x);
                FMA_F32X2(a2[i][1], uu[i], wi.y);
                FMA_F32X2(a3[i][0], vv[i], wi.x);
                FMA_F32X2(a3[i][1], vv[i], wi.y);
            }
        }
        // no trailing sync needed: next round's first __syncthreads() orders
        // this round's smem reads against next round's writes
    }

    // ---- epilogue: per-CTA partials -> global hist via atomics ----
    float* h = g_hist + img * 3 * (DH * DH);
#pragma unroll
    for (int i = 0; i < 4; i++)
#pragma unroll
        for (int j = 0; j < 2; j++) {
            int idx = (4 * ty + i) * DH + 4 * tx + 2 * j;
            float lo, hi;
            UNPACK2(lo, hi, a1[i][j]);
            atomicAdd(h + idx,     lo);
            atomicAdd(h + idx + 1, hi);
            UNPACK2(lo, hi, a2[i][j]);
            atomicAdd(h + 1 * DH * DH + idx,     lo);
            atomicAdd(h + 1 * DH * DH + idx + 1, hi);
            UNPACK2(lo, hi, a3[i][j]);
            atomicAdd(h + 2 * DH * DH + idx,     lo);
            atomicAdd(h + 2 * DH * DH + idx + 1, hi);
        }
}

// ---------------------------------------------------------------------------
// Per-batch Hellinger reduction: one block per batch element.
// ---------------------------------------------------------------------------
__global__ void reduce_kernel()
{
    __shared__ float red[256];
    __shared__ float sSx, sSy;
    const int b   = blockIdx.x;
    const int tid = threadIdx.x;
    const float* hx = g_hist + (size_t)b       * (3 * DH * DH);
    const float* hy = g_hist + (size_t)(8 + b) * (3 * DH * DH);

    float sx = 0.f, sy = 0.f;
    for (int i = tid; i < 3 * DH * DH; i += 256) { sx += hx[i]; sy += hy[i]; }

    red[tid] = sx; __syncthreads();
    for (int s = 128; s > 0; s >>= 1) { if (tid < s) red[tid] += red[tid + s]; __syncthreads(); }
    if (tid == 0) sSx = red[0];
    __syncthreads();

    red[tid] = sy; __syncthreads();
    for (int s = 128; s > 0; s >>= 1) { if (tid < s) red[tid] += red[tid + s]; __syncthreads(); }
    if (tid == 0) sSy = red[0];
    __syncthreads();

    const float rx = 1.0f / sSx;
    const float ry = 1.0f / sSy;

    float ss = 0.f;
    for (int i = tid; i < 3 * DH * DH; i += 256) {
        float d = sqrtf(hy[i] * ry) - sqrtf(hx[i] * rx);
        ss = fmaf(d, d, ss);
    }
    red[tid] = ss; __syncthreads();
    for (int s = 128; s > 0; s >>= 1) { if (tid < s) red[tid] += red[tid + s]; __syncthreads(); }
    if (tid == 0) g_hn[b] = sqrtf(red[0]) * 0.70710678118654752f;  // sqrt(0.5)
}

__global__ void final_kernel(float* __restrict__ out)
{
    float s = 0.f;
#pragma unroll
    for (int b = 0; b < 8; b++) s += g_hn[b];
    out[0] = s * 0.125f;
}

// ---------------------------------------------------------------------------
extern "C" void kernel_launch(void* const* d_in, const int* in_sizes, int n_in,
                              void* d_out, int out_size)
{
    const float* x = (const float*)d_in[0];
    const float* y = (const float*)d_in[1];

    void* hptr = nullptr;
    cudaGetSymbolAddress(&hptr, g_hist);
    cudaMemsetAsync(hptr, 0, sizeof(float) * NIMG * 3 * DH * DH);

    hist_kernel<<<NIMG * CH, 256>>>(x, y);
    reduce_kernel<<<8, 256>>>();
    final_kernel<<<1, 1>>>((float*)d_out);
}

// round 7
// speedup vs baseline: 6.1302x; 3.9169x over previous
#include <cuda_runtime.h>
#include <cuda_fp16.h>
#include <math.h>
#include <stdint.h>

#define NIMG 16
#define NPIX 65536
#define DH 64
#define PB 64                  // pixels per chunk (K per MMA round)
#define CPI 18                 // CTAs per image -> 288 CTAs, 2/SM
#define NCHUNK (NPIX / PB)     // 1024

__device__ float g_hist[NIMG * 3 * DH * DH];   // [img][3][64][64] (permuted bins; loss-invariant)
__device__ float g_hn[8];

// m16n8k16 f16 MMA, f32 accumulate (sm_80 feature -> compiles at plain sm_103 PTX target)
__device__ __forceinline__ void mma16816(float* c, const uint32_t* a, const uint32_t* b) {
    asm volatile(
        "mma.sync.aligned.m16n8k16.row.col.f32.f16.f16.f32 "
        "{%0,%1,%2,%3}, {%4,%5,%6,%7}, {%8,%9}, {%0,%1,%2,%3};"
        : "+f"(c[0]), "+f"(c[1]), "+f"(c[2]), "+f"(c[3])
        : "r"(a[0]), "r"(a[1]), "r"(a[2]), "r"(a[3]), "r"(b[0]), "r"(b[1]));
}

// ---------------------------------------------------------------------------
// GEMM-as-histogram: per image D[128,128] = A.B^T over K=pixels.
//   A rows 0-63 = w(ur) per bin ("U"), rows 64-127 = w(vr) ("V")
//   B rows 0-63 = iy*w(vr), rows 64-127 = iy*w(lg-lb) ("W")
//   D blocks: (U,V)=H1, (U,W)=H2, (V,W)=H3; (V,V) block skipped entirely.
// Smem layout (per operand, f16x2 words): word(row,kp) at
//   ((kp>>2)*16 + (row>>3))*32 + (kp&3)*8 + (row&7)
// -> every fragment load and every weight store hits 32 distinct banks.
// ---------------------------------------------------------------------------
__global__ __launch_bounds__(256, 2)
void hist_kernel(const float* __restrict__ x, const float* __restrict__ y)
{
    __shared__ __half2 sA[4096];   // 128 rows x 32 kp (16 KB)
    __shared__ __half2 sB[4096];   // 16 KB
    __shared__ float   sPix[192];  // [fam 0..2][64 px]: U, V, W coords
    __shared__ float   sIy[64];

    const int tid  = threadIdx.x;
    const int wid  = tid >> 5;
    const int lane = tid & 31;
    const int wm   = wid >> 2;     // 0..1 : 64-row slab
    const int wn   = wid & 3;      // 0..3 : 32-col slab
    const bool mma_active = !(wm == 1 && wn < 2);   // skip (V,iyV) waste quadrant

    const int img = blockIdx.x / CPI;
    const int c0  = blockIdx.x - img * CPI;
    const float* base = (img < 8 ? x : y) + (size_t)(img & 7) * (3 * NPIX);

    const int laneoff = (lane & 3) * 8 + (lane >> 2);   // conflict-free bank perm

    float acc[4][4][4];   // [m16 subtile][n8 subtile][reg]
#pragma unroll
    for (int mi = 0; mi < 4; mi++)
#pragma unroll
        for (int ni = 0; ni < 4; ni++)
#pragma unroll
            for (int r = 0; r < 4; r++) acc[mi][ni][r] = 0.f;

    for (int t = c0; t < NCHUNK; t += CPI) {
        // ---- stage 64 pixels ----
        if (tid < PB) {
            int n = t * PB + tid;
            float r = base[n]            + 1e-6f;
            float g = base[NPIX + n]     + 1e-6f;
            float b = base[2 * NPIX + n] + 1e-6f;
            float lr = __logf(r), lg = __logf(g), lb = __logf(b);
            sPix[tid]       = lr - lg;   // ur (U)
            sPix[64 + tid]  = lr - lb;   // vr (V)
            sPix[128 + tid] = lg - lb;   // W
            sIy[tid]        = sqrtf(fmaf(r, r, fmaf(g, g, b * b)));
        }
        __syncthreads();

        // ---- weight generation: 24 iterations x 256 threads ----
        // it -> bin-block (8 bins, fam uniform); warp -> kp word-block (4 words)
#pragma unroll
        for (int it = 0; it < 24; it++) {
            int b   = it * 8 + (lane & 7);      // 0..191 (fam = b>>6, uniform per it)
            int ww  = wid * 4 + (lane >> 3);    // kp word 0..31 (pixels 2ww, 2ww+1)
            int fam = b >> 6;
            int j   = b & 63;
            float c50 = fmaf((float)j, 300.0f / 63.0f, -150.0f);  // 50*center_j
            float p0 = sPix[fam * 64 + 2 * ww];
            float p1 = sPix[fam * 64 + 2 * ww + 1];
            float d0 = fmaf(p0, 50.0f, -c50);
            float d1 = fmaf(p1, 50.0f, -c50);
            float w0 = __fdividef(1.0f, fmaf(d0, d0, 1.0f));
            float w1 = __fdividef(1.0f, fmaf(d1, d1, 1.0f));
            int wordo = ((ww >> 2) * 16) * 32 + (ww & 3) * 8;
            if (fam <= 1) {                     // U, V -> A rows 0..127
                int row = b;
                sA[wordo + ((row >> 3) << 5) + (row & 7)] = __floats2half2_rn(w0, w1);
            }
            if (fam >= 1) {                     // V, W -> B rows 0..127 (x iy)
                int row = b - 64;
                float i0 = sIy[2 * ww], i1 = sIy[2 * ww + 1];
                sB[wordo + ((row >> 3) << 5) + (row & 7)] = __floats2half2_rn(w0 * i0, w1 * i1);
            }
        }
        __syncthreads();

        // ---- MMA phase: 4 k-steps of K=16 ----
        if (mma_active) {
#pragma unroll
            for (int ks = 0; ks < 4; ks++) {
                uint32_t af[4][4], bf[4][2];
#pragma unroll
                for (int mi = 0; mi < 4; mi++)
#pragma unroll
                    for (int r = 0; r < 4; r++) {
                        int blk = (ks * 2 + (r >> 1)) * 16 + wm * 8 + mi * 2 + (r & 1);
                        af[mi][r] = *(const uint32_t*)&sA[blk * 32 + laneoff];
                    }
#pragma unroll
                for (int ni = 0; ni < 4; ni++)
#pragma unroll
                    for (int r = 0; r < 2; r++) {
                        int blk = (ks * 2 + r) * 16 + wn * 4 + ni;
                        bf[ni][r] = *(const uint32_t*)&sB[blk * 32 + laneoff];
                    }
#pragma unroll
                for (int mi = 0; mi < 4; mi++)
#pragma unroll
                    for (int ni = 0; ni < 4; ni++)
                        mma16816(acc[mi][ni], af[mi], bf[ni]);
            }
        }
        __syncthreads();   // protect sA/sB/sPix before next chunk overwrites
    }

    // ---- epilogue: register accumulators -> g_hist via RED.ADD ----
    if (mma_active) {
        float* h = g_hist + img * 3 * (DH * DH);
#pragma unroll
        for (int mi = 0; mi < 4; mi++)
#pragma unroll
            for (int ni = 0; ni < 4; ni++)
#pragma unroll
                for (int r = 0; r < 4; r++) {
                    int row = wm * 64 + mi * 16 + (lane >> 2) + 8 * (r >> 1);
                    int col = wn * 32 + ni * 8 + (lane & 3) * 2 + (r & 1);
                    int idx;
                    if (row < 64) idx = (col < 64) ? (row * DH + col)
                                                   : (DH * DH + row * DH + (col - 64));
                    else          idx = 2 * DH * DH + (row - 64) * DH + (col - 64);
                    atomicAdd(h + idx, acc[mi][ni][r]);
                }
    }
}

// ---------------------------------------------------------------------------
// Per-batch Hellinger reduction: one block per batch element.
// ---------------------------------------------------------------------------
__global__ void reduce_kernel()
{
    __shared__ float red[256];
    __shared__ float sSx, sSy;
    const int b   = blockIdx.x;
    const int tid = threadIdx.x;
    const float* hx = g_hist + (size_t)b       * (3 * DH * DH);
    const float* hy = g_hist + (size_t)(8 + b) * (3 * DH * DH);

    float sx = 0.f, sy = 0.f;
    for (int i = tid; i < 3 * DH * DH; i += 256) { sx += hx[i]; sy += hy[i]; }

    red[tid] = sx; __syncthreads();
    for (int s = 128; s > 0; s >>= 1) { if (tid < s) red[tid] += red[tid + s]; __syncthreads(); }
    if (tid == 0) sSx = red[0];
    __syncthreads();

    red[tid] = sy; __syncthreads();
    for (int s = 128; s > 0; s >>= 1) { if (tid < s) red[tid] += red[tid + s]; __syncthreads(); }
    if (tid == 0) sSy = red[0];
    __syncthreads();

    const float rx = 1.0f / sSx;
    const float ry = 1.0f / sSy;

    float ss = 0.f;
    for (int i = tid; i < 3 * DH * DH; i += 256) {
        float d = sqrtf(hy[i] * ry) - sqrtf(hx[i] * rx);
        ss = fmaf(d, d, ss);
    }
    red[tid] = ss; __syncthreads();
    for (int s = 128; s > 0; s >>= 1) { if (tid < s) red[tid] += red[tid + s]; __syncthreads(); }
    if (tid == 0) g_hn[b] = sqrtf(red[0]) * 0.70710678118654752f;  // sqrt(0.5)
}

__global__ void final_kernel(float* __restrict__ out)
{
    float s = 0.f;
#pragma unroll
    for (int b = 0; b < 8; b++) s += g_hn[b];
    out[0] = s * 0.125f;
}

// ---------------------------------------------------------------------------
extern "C" void kernel_launch(void* const* d_in, const int* in_sizes, int n_in,
                              void* d_out, int out_size)
{
    const float* x = (const float*)d_in[0];
    const float* y = (const float*)d_in[1];

    void* hptr = nullptr;
    cudaGetSymbolAddress(&hptr, g_hist);
    cudaMemsetAsync(hptr, 0, sizeof(float) * NIMG * 3 * DH * DH);

    hist_kernel<<<NIMG * CPI, 256>>>(x, y);
    reduce_kernel<<<8, 256>>>();
    final_kernel<<<1, 1>>>((float*)d_out);
}